// round 2
// baseline (speedup 1.0000x reference)
#include <cuda_runtime.h>
#include <math.h>

#define LRELU(v) ((v) > 0.f ? (v) : 0.2f * (v))

static const int MAXN = 50000;

// ---------------- scratch (allocation-free: __device__ globals) ----------------
__device__ float g_h1[MAXN * 256];   // layer1 features h = x@W1
__device__ float g_o1[MAXN * 256];   // layer1 aggregated output (then relu'd)
__device__ float g_as1[MAXN * 8];
__device__ float g_ad1[MAXN * 8];
__device__ float g_m1[MAXN * 8];
__device__ float g_s1[MAXN * 8];
__device__ float g_h2[MAXN * 32];    // layer2 features
__device__ float g_z[MAXN * 32];     // layer2 aggregated output
__device__ float g_as2[MAXN];
__device__ float g_ad2[MAXN];
__device__ float g_m2[MAXN];
__device__ float g_s2[MAXN];

// ---------------- helpers ----------------
__device__ __forceinline__ void atomicMaxF(float* addr, float val) {
    int* ai = (int*)addr;
    int old = *ai;
    while (__int_as_float(old) < val) {
        int assumed = old;
        old = atomicCAS(ai, assumed, __float_as_int(val));
        if (old == assumed) break;
    }
}

// ---------------- GEMM: C[M,N] = A[M,K] @ B[K,N] (+bias) ----------------
// 64x64 tile, BK=16, 256 threads, 4x4 microtile per thread.
// Requires K % 16 == 0 and N % 4 == 0 (true for all three GEMMs here).
__global__ void gemm_k(const float* __restrict__ A, const float* __restrict__ B,
                       const float* __restrict__ bias, float* __restrict__ C,
                       int M, int N, int K) {
    __shared__ float As[16][64];
    __shared__ float Bs[16][64];
    int tid = threadIdx.x;
    int ty = tid >> 4, tx = tid & 15;
    int m0 = blockIdx.y * 64;
    int n0 = blockIdx.x * 64;
    float acc[4][4] = {};

    for (int k0 = 0; k0 < K; k0 += 16) {
        // A tile: thread t loads float4 at (m0 + t/4, k0 + (t%4)*4), stores transposed
        {
            int ml = tid >> 2, q = (tid & 3) << 2;
            float4 v = make_float4(0.f, 0.f, 0.f, 0.f);
            if (m0 + ml < M)
                v = *(const float4*)(A + (size_t)(m0 + ml) * K + k0 + q);
            As[q + 0][ml] = v.x; As[q + 1][ml] = v.y;
            As[q + 2][ml] = v.z; As[q + 3][ml] = v.w;
        }
        // B tile: thread t loads float4 at (k0 + t/16, n0 + (t%16)*4)
        {
            int kl = tid >> 4, g = (tid & 15) << 2;
            float4 v = make_float4(0.f, 0.f, 0.f, 0.f);
            if (n0 + g < N)
                v = *(const float4*)(B + (size_t)(k0 + kl) * N + n0 + g);
            *(float4*)&Bs[kl][g] = v;
        }
        __syncthreads();
        #pragma unroll
        for (int kk = 0; kk < 16; kk++) {
            float a[4], b[4];
            #pragma unroll
            for (int i = 0; i < 4; i++) a[i] = As[kk][ty + 16 * i];
            #pragma unroll
            for (int j = 0; j < 4; j++) b[j] = Bs[kk][tx + 16 * j];
            #pragma unroll
            for (int i = 0; i < 4; i++)
                #pragma unroll
                for (int j = 0; j < 4; j++)
                    acc[i][j] += a[i] * b[j];
        }
        __syncthreads();
    }
    #pragma unroll
    for (int i = 0; i < 4; i++) {
        int row = m0 + ty + 16 * i;
        if (row >= M) continue;
        #pragma unroll
        for (int j = 0; j < 4; j++) {
            int col = n0 + tx + 16 * j;
            if (col >= N) continue;
            float v = acc[i][j];
            if (bias) v += bias[col];
            C[(size_t)row * N + col] = v;
        }
    }
}

// ---------------- per-node attention coefficients ----------------
template<int H, int C>
__global__ void alpha_k(const float* __restrict__ hf,
                        const float* __restrict__ a_src, const float* __restrict__ a_dst,
                        float* __restrict__ as, float* __restrict__ ad, int N) {
    int i = blockIdx.x * blockDim.x + threadIdx.x;
    if (i >= N * H) return;
    int n = i / H, h = i - n * H;
    const float* hp = hf + (size_t)n * H * C + h * C;
    float ss = 0.f, sd = 0.f;
    #pragma unroll
    for (int c = 0; c < C; c++) {
        float v = hp[c];
        ss += v * a_src[h * C + c];
        sd += v * a_dst[h * C + c];
    }
    as[i] = ss;
    ad[i] = sd;
}

// ---------------- init kernels ----------------
__global__ void fill_k(float* p, float v, int n) {
    int i = blockIdx.x * blockDim.x + threadIdx.x;
    if (i < n) p[i] = v;
}
__global__ void init_bias_k(float* p, const float* __restrict__ bias, int hc, int n) {
    int i = blockIdx.x * blockDim.x + threadIdx.x;
    if (i < n) p[i] = bias[i % hc];
}
__global__ void relu_k(float* p, int n) {
    int i = blockIdx.x * blockDim.x + threadIdx.x;
    if (i < n) p[i] = fmaxf(p[i], 0.f);
}

// ---------------- edge passes (self-loops = indices >= E) ----------------
// NOTE: edge_index is int32 on device (JAX x64 disabled coerces int64->int32).
template<int H>
__global__ void edge_max_k(const float* __restrict__ as, const float* __restrict__ ad,
                           float* __restrict__ m,
                           const int* __restrict__ src, const int* __restrict__ dst,
                           int E, int ET) {
    int idx = blockIdx.x * blockDim.x + threadIdx.x;
    if (idx >= ET * H) return;
    int e = idx / H, h = idx - e * H;
    int s_, d_;
    if (e < E) { s_ = src[e]; d_ = dst[e]; }
    else       { s_ = d_ = e - E; }
    float v = as[s_ * H + h] + ad[d_ * H + h];
    v = LRELU(v);
    atomicMaxF(&m[d_ * H + h], v);
}

template<int H>
__global__ void edge_sum_k(const float* __restrict__ as, const float* __restrict__ ad,
                           const float* __restrict__ m, float* __restrict__ s,
                           const int* __restrict__ src, const int* __restrict__ dst,
                           int E, int ET) {
    int idx = blockIdx.x * blockDim.x + threadIdx.x;
    if (idx >= ET * H) return;
    int e = idx / H, h = idx - e * H;
    int s_, d_;
    if (e < E) { s_ = src[e]; d_ = dst[e]; }
    else       { s_ = d_ = e - E; }
    float v = as[s_ * H + h] + ad[d_ * H + h];
    v = LRELU(v);
    atomicAdd(&s[d_ * H + h], expf(v - m[d_ * H + h]));
}

// One warp per edge; HC floats per edge, coalesced gather + coalesced atomic scatter.
template<int H, int C>
__global__ void edge_agg_k(const float* __restrict__ hf,
                           const float* __restrict__ as, const float* __restrict__ ad,
                           const float* __restrict__ m, const float* __restrict__ s,
                           float* __restrict__ out,
                           const int* __restrict__ src, const int* __restrict__ dst,
                           int E, int ET) {
    int w = (blockIdx.x * blockDim.x + threadIdx.x) >> 5;
    int lane = threadIdx.x & 31;
    if (w >= ET) return;
    int s_, d_;
    if (w < E) { s_ = src[w]; d_ = dst[w]; }
    else       { s_ = d_ = w - E; }
    const int HC = H * C;
    #pragma unroll
    for (int j = lane; j < HC; j += 32) {
        int h = j / C;
        float e = as[s_ * H + h] + ad[d_ * H + h];
        e = LRELU(e);
        float a = expf(e - m[d_ * H + h]) / (s[d_ * H + h] + 1e-16f);
        atomicAdd(&out[(size_t)d_ * HC + j], hf[(size_t)s_ * HC + j] * a);
    }
}

// ---------------- launch ----------------
extern "C" void kernel_launch(void* const* d_in, const int* in_sizes, int n_in,
                              void* d_out, int out_size) {
    const float* x   = (const float*)d_in[0];
    const int*   ei  = (const int*)d_in[1];   // int32! (JAX x64 disabled)
    const float* W1  = (const float*)d_in[2];
    const float* aS1 = (const float*)d_in[3];
    const float* aD1 = (const float*)d_in[4];
    const float* b1  = (const float*)d_in[5];
    const float* W2  = (const float*)d_in[6];
    const float* aS2 = (const float*)d_in[7];
    const float* aD2 = (const float*)d_in[8];
    const float* b2  = (const float*)d_in[9];
    const float* Wd  = (const float*)d_in[10];
    const float* bd  = (const float*)d_in[11];
    float* out = (float*)d_out;

    int N  = in_sizes[0] / 128;
    int E  = in_sizes[1] / 2;
    int ET = E + N;  // edges incl. implicit self-loops
    const int* src = ei;
    const int* dst = ei + E;

    float *h1, *o1, *as1, *ad1, *m1, *s1, *h2, *z, *as2, *ad2, *m2, *s2;
    cudaGetSymbolAddress((void**)&h1,  g_h1);
    cudaGetSymbolAddress((void**)&o1,  g_o1);
    cudaGetSymbolAddress((void**)&as1, g_as1);
    cudaGetSymbolAddress((void**)&ad1, g_ad1);
    cudaGetSymbolAddress((void**)&m1,  g_m1);
    cudaGetSymbolAddress((void**)&s1,  g_s1);
    cudaGetSymbolAddress((void**)&h2,  g_h2);
    cudaGetSymbolAddress((void**)&z,   g_z);
    cudaGetSymbolAddress((void**)&as2, g_as2);
    cudaGetSymbolAddress((void**)&ad2, g_ad2);
    cudaGetSymbolAddress((void**)&m2,  g_m2);
    cudaGetSymbolAddress((void**)&s2,  g_s2);

    const int TB = 256;
    int mb = (N + 63) / 64;

    // ===== Layer 1 (H=8, C=32) =====
    gemm_k<<<dim3((256 + 63) / 64, mb), TB>>>(x, W1, nullptr, h1, N, 256, 128);
    alpha_k<8, 32><<<(N * 8 + TB - 1) / TB, TB>>>(h1, aS1, aD1, as1, ad1, N);

    fill_k<<<(N * 8 + TB - 1) / TB, TB>>>(m1, -3.0e38f, N * 8);
    fill_k<<<(N * 8 + TB - 1) / TB, TB>>>(s1, 0.f, N * 8);
    init_bias_k<<<(N * 256 + TB - 1) / TB, TB>>>(o1, b1, 256, N * 256);

    edge_max_k<8><<<(ET * 8 + TB - 1) / TB, TB>>>(as1, ad1, m1, src, dst, E, ET);
    edge_sum_k<8><<<(ET * 8 + TB - 1) / TB, TB>>>(as1, ad1, m1, s1, src, dst, E, ET);
    {
        long long thr = (long long)ET * 32;
        edge_agg_k<8, 32><<<(unsigned)((thr + TB - 1) / TB), TB>>>(
            h1, as1, ad1, m1, s1, o1, src, dst, E, ET);
    }
    relu_k<<<(N * 256 + TB - 1) / TB, TB>>>(o1, N * 256);

    // ===== Layer 2 (H=1, C=32) =====
    gemm_k<<<dim3(1, mb), TB>>>(o1, W2, nullptr, h2, N, 32, 256);
    alpha_k<1, 32><<<(N + TB - 1) / TB, TB>>>(h2, aS2, aD2, as2, ad2, N);

    fill_k<<<(N + TB - 1) / TB, TB>>>(m2, -3.0e38f, N);
    fill_k<<<(N + TB - 1) / TB, TB>>>(s2, 0.f, N);
    init_bias_k<<<(N * 32 + TB - 1) / TB, TB>>>(z, b2, 32, N * 32);

    edge_max_k<1><<<(ET + TB - 1) / TB, TB>>>(as2, ad2, m2, src, dst, E, ET);
    edge_sum_k<1><<<(ET + TB - 1) / TB, TB>>>(as2, ad2, m2, s2, src, dst, E, ET);
    {
        long long thr = (long long)ET * 32;
        edge_agg_k<1, 32><<<(unsigned)((thr + TB - 1) / TB), TB>>>(
            h2, as2, ad2, m2, s2, z, src, dst, E, ET);
    }

    // ===== Decoder: out = z @ Wd + bd =====
    gemm_k<<<dim3(2, mb), TB>>>(z, Wd, bd, out, N, 128, 32);
}

// round 3
// speedup vs baseline: 1.4294x; 1.4294x over previous
#include <cuda_runtime.h>
#include <math.h>

static const int MAXN = 50000;
static const int MAXE = 800000 + MAXN;   // edges + self loops

// ---------------- scratch (allocation-free: __device__ globals) ----------------
__device__ float    g_h1[MAXN * 256];
__device__ float    g_o1[MAXN * 256];
__device__ float    g_as1[MAXN * 8];
__device__ float    g_ad1[MAXN * 8];
__device__ unsigned g_m1[MAXN * 8];      // order-encoded float max
__device__ float    g_s1[MAXN * 8];
__device__ float    g_e1[(size_t)MAXE * 8];  // per-edge logits -> exp values
__device__ float    g_h2[MAXN * 32];
__device__ float    g_z[MAXN * 32];
__device__ float    g_as2[MAXN];
__device__ float    g_ad2[MAXN];
__device__ unsigned g_m2[MAXN];
__device__ float    g_s2[MAXN];
__device__ float    g_e2[MAXE];

// ---------------- helpers ----------------
__device__ __forceinline__ float lrelu(float v) { return v > 0.f ? v : 0.2f * v; }

// order-preserving float<->uint so segment-max can use native atomicMax(uint)
__device__ __forceinline__ unsigned f2o(float f) {
    unsigned u = __float_as_uint(f);
    return (u & 0x80000000u) ? ~u : (u | 0x80000000u);
}
__device__ __forceinline__ float o2f(unsigned k) {
    unsigned u = (k & 0x80000000u) ? (k ^ 0x80000000u) : ~k;
    return __uint_as_float(u);
}

__device__ __forceinline__ void red4(float* p, float a, float b, float c, float d) {
    asm volatile("red.global.add.v4.f32 [%0], {%1, %2, %3, %4};"
                 :: "l"(p), "f"(a), "f"(b), "f"(c), "f"(d) : "memory");
}

// ---------------- GEMM: C[M,N] = A[M,K] @ B[K,N] (+bias), optional relu(A) ----
__global__ void gemm_k(const float* __restrict__ A, const float* __restrict__ B,
                       const float* __restrict__ bias, float* __restrict__ C,
                       int M, int N, int K, int reluA) {
    __shared__ float As[16][64];
    __shared__ float Bs[16][64];
    int tid = threadIdx.x;
    int ty = tid >> 4, tx = tid & 15;
    int m0 = blockIdx.y * 64;
    int n0 = blockIdx.x * 64;
    float acc[4][4] = {};

    for (int k0 = 0; k0 < K; k0 += 16) {
        {
            int ml = tid >> 2, q = (tid & 3) << 2;
            float4 v = make_float4(0.f, 0.f, 0.f, 0.f);
            if (m0 + ml < M)
                v = *(const float4*)(A + (size_t)(m0 + ml) * K + k0 + q);
            if (reluA) {
                v.x = fmaxf(v.x, 0.f); v.y = fmaxf(v.y, 0.f);
                v.z = fmaxf(v.z, 0.f); v.w = fmaxf(v.w, 0.f);
            }
            As[q + 0][ml] = v.x; As[q + 1][ml] = v.y;
            As[q + 2][ml] = v.z; As[q + 3][ml] = v.w;
        }
        {
            int kl = tid >> 4, g = (tid & 15) << 2;
            float4 v = make_float4(0.f, 0.f, 0.f, 0.f);
            if (n0 + g < N)
                v = *(const float4*)(B + (size_t)(k0 + kl) * N + n0 + g);
            *(float4*)&Bs[kl][g] = v;
        }
        __syncthreads();
        #pragma unroll
        for (int kk = 0; kk < 16; kk++) {
            float a[4], b[4];
            #pragma unroll
            for (int i = 0; i < 4; i++) a[i] = As[kk][ty + 16 * i];
            #pragma unroll
            for (int j = 0; j < 4; j++) b[j] = Bs[kk][tx + 16 * j];
            #pragma unroll
            for (int i = 0; i < 4; i++)
                #pragma unroll
                for (int j = 0; j < 4; j++)
                    acc[i][j] += a[i] * b[j];
        }
        __syncthreads();
    }
    #pragma unroll
    for (int i = 0; i < 4; i++) {
        int row = m0 + ty + 16 * i;
        if (row >= M) continue;
        #pragma unroll
        for (int j = 0; j < 4; j++) {
            int col = n0 + tx + 16 * j;
            if (col >= N) continue;
            float v = acc[i][j];
            if (bias) v += bias[col];
            C[(size_t)row * N + col] = v;
        }
    }
}

// ---------------- per-node attention coefficients ----------------
template<int H, int C>
__global__ void alpha_k(const float* __restrict__ hf,
                        const float* __restrict__ a_src, const float* __restrict__ a_dst,
                        float* __restrict__ as, float* __restrict__ ad, int N) {
    int i = blockIdx.x * blockDim.x + threadIdx.x;
    if (i >= N * H) return;
    int n = i / H, h = i - n * H;
    const float* hp = hf + (size_t)n * H * C + h * C;
    float ss = 0.f, sd = 0.f;
    #pragma unroll
    for (int c = 0; c < C; c++) {
        float v = hp[c];
        ss += v * a_src[h * C + c];
        sd += v * a_dst[h * C + c];
    }
    as[i] = ss;
    ad[i] = sd;
}

// ---------------- init ----------------
__global__ void init_ms_k(unsigned* m1, float* s1, unsigned* m2, float* s2, int N) {
    int i = blockIdx.x * blockDim.x + threadIdx.x;
    if (i < N * 8) { m1[i] = 0u; s1[i] = 0.f; }
    if (i < N)     { m2[i] = 0u; s2[i] = 0.f; }
}
__global__ void init_bias_k(float* p, const float* __restrict__ bias, int hc, int n) {
    int i = blockIdx.x * blockDim.x + threadIdx.x;
    if (i < n) p[i] = bias[i % hc];
}

// ---------------- edge pass 1: logits + segment max (H=8) ----------------
__global__ void edge_logit8_k(const float4* __restrict__ as4, const float4* __restrict__ ad4,
                              unsigned* __restrict__ m, float* __restrict__ ge,
                              const int* __restrict__ src, const int* __restrict__ dst,
                              int E, int ET) {
    int e = blockIdx.x * blockDim.x + threadIdx.x;
    if (e >= ET) return;
    int s_, d_;
    if (e < E) { s_ = src[e]; d_ = dst[e]; } else { s_ = d_ = e - E; }
    float4 a0 = as4[s_ * 2], a1 = as4[s_ * 2 + 1];
    float4 b0 = ad4[d_ * 2], b1 = ad4[d_ * 2 + 1];
    float4 v0, v1;
    v0.x = lrelu(a0.x + b0.x); v0.y = lrelu(a0.y + b0.y);
    v0.z = lrelu(a0.z + b0.z); v0.w = lrelu(a0.w + b0.w);
    v1.x = lrelu(a1.x + b1.x); v1.y = lrelu(a1.y + b1.y);
    v1.z = lrelu(a1.z + b1.z); v1.w = lrelu(a1.w + b1.w);
    unsigned* mp = m + d_ * 8;
    atomicMax(mp + 0, f2o(v0.x)); atomicMax(mp + 1, f2o(v0.y));
    atomicMax(mp + 2, f2o(v0.z)); atomicMax(mp + 3, f2o(v0.w));
    atomicMax(mp + 4, f2o(v1.x)); atomicMax(mp + 5, f2o(v1.y));
    atomicMax(mp + 6, f2o(v1.z)); atomicMax(mp + 7, f2o(v1.w));
    float4* gp = (float4*)(ge + (size_t)e * 8);
    gp[0] = v0; gp[1] = v1;
}

// H=1 variant
__global__ void edge_logit1_k(const float* __restrict__ as, const float* __restrict__ ad,
                              unsigned* __restrict__ m, float* __restrict__ ge,
                              const int* __restrict__ src, const int* __restrict__ dst,
                              int E, int ET) {
    int e = blockIdx.x * blockDim.x + threadIdx.x;
    if (e >= ET) return;
    int s_, d_;
    if (e < E) { s_ = src[e]; d_ = dst[e]; } else { s_ = d_ = e - E; }
    float v = lrelu(as[s_] + ad[d_]);
    atomicMax(m + d_, f2o(v));
    ge[e] = v;
}

// ---------------- edge pass 2: exp + segment sum ----------------
template<int LOGH>
__global__ void edge_expsum_k(float* __restrict__ ge, const unsigned* __restrict__ m,
                              float* __restrict__ s, const int* __restrict__ dst,
                              int E, int ET) {
    int idx = blockIdx.x * blockDim.x + threadIdx.x;
    if (idx >= (ET << LOGH)) return;
    int e = idx >> LOGH, h = idx & ((1 << LOGH) - 1);
    int d_ = (e < E) ? __ldg(dst + e) : e - E;
    int mi = (d_ << LOGH) + h;
    float ex = expf(ge[idx] - o2f(m[mi]));
    ge[idx] = ex;
    atomicAdd(&s[mi], ex);
}

// ---------------- edge pass 3: aggregate (H=8, C=32: warp per edge) ---------
__global__ void edge_agg8_k(const float* __restrict__ hf, const float* __restrict__ ge,
                            const float* __restrict__ s, float* __restrict__ out,
                            const int* __restrict__ src, const int* __restrict__ dst,
                            int E, int ET) {
    int w = (blockIdx.x * blockDim.x + threadIdx.x) >> 5;
    int lane = threadIdx.x & 31;
    if (w >= ET) return;
    int s_, d_;
    if (w < E) { s_ = src[w]; d_ = dst[w]; } else { s_ = d_ = w - E; }
    float alpha = 0.f;
    if (lane < 8) {
        float ex = ge[(size_t)w * 8 + lane];
        alpha = ex / (s[d_ * 8 + lane] + 1e-16f);
    }
    const float4* hp = (const float4*)(hf + (size_t)s_ * 256);
    float* op = out + (size_t)d_ * 256;
    #pragma unroll
    for (int i = 0; i < 2; i++) {
        int f = lane + 32 * i;                      // float4 index 0..63
        float a = __shfl_sync(0xffffffffu, alpha, f >> 3);  // head = (4f)/32
        float4 v = hp[f];
        red4(op + 4 * f, v.x * a, v.y * a, v.z * a, v.w * a);
    }
}

// (H=1, C=32: 8 lanes per edge, one float4 each)
__global__ void edge_agg1_k(const float* __restrict__ hf, const float* __restrict__ ge,
                            const float* __restrict__ s, float* __restrict__ out,
                            const int* __restrict__ src, const int* __restrict__ dst,
                            int E, int ET) {
    int t = blockIdx.x * blockDim.x + threadIdx.x;
    int e = t >> 3, l8 = t & 7;
    if (e >= ET) return;
    int s_, d_;
    if (e < E) { s_ = src[e]; d_ = dst[e]; } else { s_ = d_ = e - E; }
    float alpha = ge[e] / (s[d_] + 1e-16f);
    float4 v = ((const float4*)(hf + (size_t)s_ * 32))[l8];
    red4(out + (size_t)d_ * 32 + 4 * l8, v.x * alpha, v.y * alpha, v.z * alpha, v.w * alpha);
}

// ---------------- launch ----------------
extern "C" void kernel_launch(void* const* d_in, const int* in_sizes, int n_in,
                              void* d_out, int out_size) {
    const float* x   = (const float*)d_in[0];
    const int*   ei  = (const int*)d_in[1];   // int32 (JAX x64 disabled)
    const float* W1  = (const float*)d_in[2];
    const float* aS1 = (const float*)d_in[3];
    const float* aD1 = (const float*)d_in[4];
    const float* b1  = (const float*)d_in[5];
    const float* W2  = (const float*)d_in[6];
    const float* aS2 = (const float*)d_in[7];
    const float* aD2 = (const float*)d_in[8];
    const float* b2  = (const float*)d_in[9];
    const float* Wd  = (const float*)d_in[10];
    const float* bd  = (const float*)d_in[11];
    float* out = (float*)d_out;

    int N  = in_sizes[0] / 128;
    int E  = in_sizes[1] / 2;
    int ET = E + N;
    const int* src = ei;
    const int* dst = ei + E;

    float *h1, *o1, *as1, *ad1, *s1, *h2, *z, *as2, *ad2, *s2, *e1, *e2;
    unsigned *m1, *m2;
    cudaGetSymbolAddress((void**)&h1,  g_h1);
    cudaGetSymbolAddress((void**)&o1,  g_o1);
    cudaGetSymbolAddress((void**)&as1, g_as1);
    cudaGetSymbolAddress((void**)&ad1, g_ad1);
    cudaGetSymbolAddress((void**)&m1,  g_m1);
    cudaGetSymbolAddress((void**)&s1,  g_s1);
    cudaGetSymbolAddress((void**)&e1,  g_e1);
    cudaGetSymbolAddress((void**)&h2,  g_h2);
    cudaGetSymbolAddress((void**)&z,   g_z);
    cudaGetSymbolAddress((void**)&as2, g_as2);
    cudaGetSymbolAddress((void**)&ad2, g_ad2);
    cudaGetSymbolAddress((void**)&m2,  g_m2);
    cudaGetSymbolAddress((void**)&s2,  g_s2);
    cudaGetSymbolAddress((void**)&e2,  g_e2);

    const int TB = 256;
    int mb = (N + 63) / 64;

    // init (1-2)
    init_ms_k<<<(N * 8 + TB - 1) / TB, TB>>>(m1, s1, m2, s2, N);
    init_bias_k<<<(N * 256 + TB - 1) / TB, TB>>>(o1, b1, 256, N * 256);

    // ===== Layer 1 (H=8, C=32) =====
    gemm_k<<<dim3(4, mb), TB>>>(x, W1, nullptr, h1, N, 256, 128, 0);           // 3
    alpha_k<8, 32><<<(N * 8 + TB - 1) / TB, TB>>>(h1, aS1, aD1, as1, ad1, N);  // 4
    init_bias_k<<<(N * 32 + TB - 1) / TB, TB>>>(z, b2, 32, N * 32);            // 5
    edge_logit8_k<<<(ET + TB - 1) / TB, TB>>>((const float4*)as1, (const float4*)ad1,
                                              m1, e1, src, dst, E, ET);        // 6
    edge_expsum_k<3><<<(ET * 8 + TB - 1) / TB, TB>>>(e1, m1, s1, dst, E, ET);  // 7
    edge_agg8_k<<<(unsigned)(((long long)ET * 32 + TB - 1) / TB), TB>>>(
        h1, e1, s1, o1, src, dst, E, ET);                                      // 8

    // ===== Layer 2 (H=1, C=32) — relu fused into GEMM A-load =====
    gemm_k<<<dim3(1, mb), TB>>>(o1, W2, nullptr, h2, N, 32, 256, 1);           // 9
    alpha_k<1, 32><<<(N + TB - 1) / TB, TB>>>(h2, aS2, aD2, as2, ad2, N);      // 10
    edge_logit1_k<<<(ET + TB - 1) / TB, TB>>>(as2, ad2, m2, e2, src, dst, E, ET);
    edge_expsum_k<0><<<(ET + TB - 1) / TB, TB>>>(e2, m2, s2, dst, E, ET);
    edge_agg1_k<<<(unsigned)(((long long)ET * 8 + TB - 1) / TB), TB>>>(
        h2, e2, s2, z, src, dst, E, ET);

    // ===== Decoder: out = z @ Wd + bd =====
    gemm_k<<<dim3(2, mb), TB>>>(z, Wd, bd, out, N, 128, 32, 0);
}

// round 4
// speedup vs baseline: 1.8315x; 1.2813x over previous
#include <cuda_runtime.h>
#include <math.h>

static const int MAXN = 50000;
static const int MAXE = 800000 + MAXN;   // edges + self loops

// ---------------- scratch (allocation-free: __device__ globals) ----------------
__device__ float    g_h1[MAXN * 256];
__device__ float    g_o1[MAXN * 256];
__device__ float    g_as1[MAXN * 8];
__device__ float    g_ad1[MAXN * 8];
__device__ unsigned g_m1[MAXN * 8];      // order-encoded float max
__device__ float    g_s1[MAXN * 8];
__device__ float    g_e1[(size_t)MAXE * 8];  // per-edge logits -> exp values
__device__ float    g_h2[MAXN * 32];
__device__ float    g_z[MAXN * 32];
__device__ float    g_as2[MAXN];
__device__ float    g_ad2[MAXN];
__device__ unsigned g_m2[MAXN];
__device__ float    g_s2[MAXN];
__device__ float    g_e2[MAXE];

// ---------------- helpers ----------------
__device__ __forceinline__ float lrelu(float v) { return v > 0.f ? v : 0.2f * v; }

__device__ __forceinline__ unsigned f2o(float f) {
    unsigned u = __float_as_uint(f);
    return (u & 0x80000000u) ? ~u : (u | 0x80000000u);
}
__device__ __forceinline__ float o2f(unsigned k) {
    unsigned u = (k & 0x80000000u) ? (k ^ 0x80000000u) : ~k;
    return __uint_as_float(u);
}

__device__ __forceinline__ void red4(float* p, float a, float b, float c, float d) {
    asm volatile("red.global.add.v4.f32 [%0], {%1, %2, %3, %4};"
                 :: "l"(p), "f"(a), "f"(b), "f"(c), "f"(d) : "memory");
}

// ---------------- GEMM: C[M,N] = A[M,K] @ B[K,N] (+bias), optional relu(A) ----
// 128x64 tile, BK=16, 256 threads, 8x4 microtile, vectorized smem access.
// Requires K % 16 == 0, N % 4 == 0.
__global__ void gemm_k(const float* __restrict__ A, const float* __restrict__ B,
                       const float* __restrict__ bias, float* __restrict__ C,
                       int M, int N, int K, int reluA) {
    __shared__ float As[16][132];   // +4 pad, keeps 16B alignment per row
    __shared__ float Bs[16][64];
    int tid = threadIdx.x;
    int ty = tid >> 4;              // 0..15 -> rows ty*8 .. ty*8+7
    int tx = tid & 15;              // 0..15 -> cols tx*4 .. tx*4+3
    int m0 = blockIdx.y * 128;
    int n0 = blockIdx.x * 64;
    float acc[8][4] = {};

    for (int k0 = 0; k0 < K; k0 += 16) {
        // A tile: 128x16 floats, 2 float4 loads per thread, stored k-major.
        #pragma unroll
        for (int i = 0; i < 2; i++) {
            int L = tid + 256 * i;
            int row = L >> 2, q = (L & 3) << 2;
            float4 v = make_float4(0.f, 0.f, 0.f, 0.f);
            if (m0 + row < M) {
                v = *(const float4*)(A + (size_t)(m0 + row) * K + k0 + q);
                if (reluA) {
                    v.x = fmaxf(v.x, 0.f); v.y = fmaxf(v.y, 0.f);
                    v.z = fmaxf(v.z, 0.f); v.w = fmaxf(v.w, 0.f);
                }
            }
            As[q + 0][row] = v.x; As[q + 1][row] = v.y;
            As[q + 2][row] = v.z; As[q + 3][row] = v.w;
        }
        // B tile: 16x64 floats, 1 float4 per thread.
        {
            int kl = tid >> 4, g = (tid & 15) << 2;
            float4 v = make_float4(0.f, 0.f, 0.f, 0.f);
            if (n0 + g < N)
                v = *(const float4*)(B + (size_t)(k0 + kl) * N + n0 + g);
            *(float4*)&Bs[kl][g] = v;
        }
        __syncthreads();
        #pragma unroll
        for (int kk = 0; kk < 16; kk++) {
            float a[8], b[4];
            *(float4*)&a[0] = *(const float4*)&As[kk][ty * 8];
            *(float4*)&a[4] = *(const float4*)&As[kk][ty * 8 + 4];
            *(float4*)&b[0] = *(const float4*)&Bs[kk][tx * 4];
            #pragma unroll
            for (int i = 0; i < 8; i++)
                #pragma unroll
                for (int j = 0; j < 4; j++)
                    acc[i][j] += a[i] * b[j];
        }
        __syncthreads();
    }
    int colb = n0 + tx * 4;
    if (colb < N) {
        float4 bv = make_float4(0.f, 0.f, 0.f, 0.f);
        if (bias) bv = *(const float4*)(bias + colb);
        #pragma unroll
        for (int i = 0; i < 8; i++) {
            int row = m0 + ty * 8 + i;
            if (row >= M) break;
            float4 v = make_float4(acc[i][0] + bv.x, acc[i][1] + bv.y,
                                   acc[i][2] + bv.z, acc[i][3] + bv.w);
            *(float4*)(C + (size_t)row * N + colb) = v;
        }
    }
}

// ---------------- attention coefficients, H=8 C=32: warp per node ----------
__global__ void alpha8_k(const float4* __restrict__ hf4,
                         const float4* __restrict__ s4, const float4* __restrict__ d4,
                         float* __restrict__ as, float* __restrict__ ad, int N) {
    int w = (blockIdx.x * blockDim.x + threadIdx.x) >> 5;
    int l = threadIdx.x & 31;
    if (w >= N) return;
    float4 cs0 = s4[l], cs1 = s4[l + 32];
    float4 cd0 = d4[l], cd1 = d4[l + 32];
    float4 h0 = hf4[(size_t)w * 64 + l];
    float4 h1 = hf4[(size_t)w * 64 + 32 + l];
    float ps0 = h0.x * cs0.x + h0.y * cs0.y + h0.z * cs0.z + h0.w * cs0.w;
    float pd0 = h0.x * cd0.x + h0.y * cd0.y + h0.z * cd0.z + h0.w * cd0.w;
    float ps1 = h1.x * cs1.x + h1.y * cs1.y + h1.z * cs1.z + h1.w * cs1.w;
    float pd1 = h1.x * cd1.x + h1.y * cd1.y + h1.z * cd1.z + h1.w * cd1.w;
    #pragma unroll
    for (int off = 4; off; off >>= 1) {
        ps0 += __shfl_xor_sync(0xffffffffu, ps0, off);
        pd0 += __shfl_xor_sync(0xffffffffu, pd0, off);
        ps1 += __shfl_xor_sync(0xffffffffu, ps1, off);
        pd1 += __shfl_xor_sync(0xffffffffu, pd1, off);
    }
    if ((l & 7) == 0) {
        int g = l >> 3;   // 0..3
        as[w * 8 + g] = ps0; as[w * 8 + 4 + g] = ps1;
        ad[w * 8 + g] = pd0; ad[w * 8 + 4 + g] = pd1;
    }
}

// H=1 C=32: 8 lanes per node
__global__ void alpha1_k(const float4* __restrict__ hf4,
                         const float4* __restrict__ s4, const float4* __restrict__ d4,
                         float* __restrict__ as, float* __restrict__ ad, int N) {
    int t = blockIdx.x * blockDim.x + threadIdx.x;
    int n = t >> 3, q = t & 7;
    if (n >= N) return;
    float4 cs = s4[q], cd = d4[q];
    float4 h = hf4[(size_t)n * 8 + q];
    float ps = h.x * cs.x + h.y * cs.y + h.z * cs.z + h.w * cs.w;
    float pd = h.x * cd.x + h.y * cd.y + h.z * cd.z + h.w * cd.w;
    #pragma unroll
    for (int off = 4; off; off >>= 1) {
        ps += __shfl_xor_sync(0xffffffffu, ps, off);
        pd += __shfl_xor_sync(0xffffffffu, pd, off);
    }
    if (q == 0) { as[n] = ps; ad[n] = pd; }
}

// ---------------- init ----------------
__global__ void init_ms_k(unsigned* m1, float* s1, unsigned* m2, float* s2, int N) {
    int i = blockIdx.x * blockDim.x + threadIdx.x;
    if (i < N * 8) { m1[i] = 0u; s1[i] = 0.f; }
    if (i < N)     { m2[i] = 0u; s2[i] = 0.f; }
}
__global__ void init_bias_k(float* p, const float* __restrict__ bias, int hc, int n) {
    int i = blockIdx.x * blockDim.x + threadIdx.x;
    if (i < n) p[i] = bias[i % hc];
}

// ---------------- edge pass 1: logits + segment max ----------------
__global__ void edge_logit8_k(const float4* __restrict__ as4, const float4* __restrict__ ad4,
                              unsigned* __restrict__ m, float* __restrict__ ge,
                              const int* __restrict__ src, const int* __restrict__ dst,
                              int E, int ET) {
    int e = blockIdx.x * blockDim.x + threadIdx.x;
    if (e >= ET) return;
    int s_, d_;
    if (e < E) { s_ = src[e]; d_ = dst[e]; } else { s_ = d_ = e - E; }
    float4 a0 = as4[s_ * 2], a1 = as4[s_ * 2 + 1];
    float4 b0 = ad4[d_ * 2], b1 = ad4[d_ * 2 + 1];
    float4 v0, v1;
    v0.x = lrelu(a0.x + b0.x); v0.y = lrelu(a0.y + b0.y);
    v0.z = lrelu(a0.z + b0.z); v0.w = lrelu(a0.w + b0.w);
    v1.x = lrelu(a1.x + b1.x); v1.y = lrelu(a1.y + b1.y);
    v1.z = lrelu(a1.z + b1.z); v1.w = lrelu(a1.w + b1.w);
    unsigned* mp = m + d_ * 8;
    atomicMax(mp + 0, f2o(v0.x)); atomicMax(mp + 1, f2o(v0.y));
    atomicMax(mp + 2, f2o(v0.z)); atomicMax(mp + 3, f2o(v0.w));
    atomicMax(mp + 4, f2o(v1.x)); atomicMax(mp + 5, f2o(v1.y));
    atomicMax(mp + 6, f2o(v1.z)); atomicMax(mp + 7, f2o(v1.w));
    float4* gp = (float4*)(ge + (size_t)e * 8);
    gp[0] = v0; gp[1] = v1;
}

__global__ void edge_logit1_k(const float* __restrict__ as, const float* __restrict__ ad,
                              unsigned* __restrict__ m, float* __restrict__ ge,
                              const int* __restrict__ src, const int* __restrict__ dst,
                              int E, int ET) {
    int e = blockIdx.x * blockDim.x + threadIdx.x;
    if (e >= ET) return;
    int s_, d_;
    if (e < E) { s_ = src[e]; d_ = dst[e]; } else { s_ = d_ = e - E; }
    float v = lrelu(as[s_] + ad[d_]);
    atomicMax(m + d_, f2o(v));
    ge[e] = v;
}

// ---------------- edge pass 2: exp + segment sum ----------------
template<int LOGH>
__global__ void edge_expsum_k(float* __restrict__ ge, const unsigned* __restrict__ m,
                              float* __restrict__ s, const int* __restrict__ dst,
                              int E, int ET) {
    int idx = blockIdx.x * blockDim.x + threadIdx.x;
    if (idx >= (ET << LOGH)) return;
    int e = idx >> LOGH, h = idx & ((1 << LOGH) - 1);
    int d_ = (e < E) ? __ldg(dst + e) : e - E;
    int mi = (d_ << LOGH) + h;
    float ex = expf(ge[idx] - o2f(m[mi]));
    ge[idx] = ex;
    atomicAdd(&s[mi], ex);
}

// ---------------- edge pass 3: aggregate ----------------
__global__ void edge_agg8_k(const float* __restrict__ hf, const float* __restrict__ ge,
                            const float* __restrict__ s, float* __restrict__ out,
                            const int* __restrict__ src, const int* __restrict__ dst,
                            int E, int ET) {
    int w = (blockIdx.x * blockDim.x + threadIdx.x) >> 5;
    int lane = threadIdx.x & 31;
    if (w >= ET) return;
    int s_, d_;
    if (w < E) { s_ = src[w]; d_ = dst[w]; } else { s_ = d_ = w - E; }
    float alpha = 0.f;
    if (lane < 8) {
        float ex = ge[(size_t)w * 8 + lane];
        alpha = ex / (s[d_ * 8 + lane] + 1e-16f);
    }
    const float4* hp = (const float4*)(hf + (size_t)s_ * 256);
    float* op = out + (size_t)d_ * 256;
    #pragma unroll
    for (int i = 0; i < 2; i++) {
        int f = lane + 32 * i;
        float a = __shfl_sync(0xffffffffu, alpha, f >> 3);
        float4 v = hp[f];
        red4(op + 4 * f, v.x * a, v.y * a, v.z * a, v.w * a);
    }
}

__global__ void edge_agg1_k(const float* __restrict__ hf, const float* __restrict__ ge,
                            const float* __restrict__ s, float* __restrict__ out,
                            const int* __restrict__ src, const int* __restrict__ dst,
                            int E, int ET) {
    int t = blockIdx.x * blockDim.x + threadIdx.x;
    int e = t >> 3, l8 = t & 7;
    if (e >= ET) return;
    int s_, d_;
    if (e < E) { s_ = src[e]; d_ = dst[e]; } else { s_ = d_ = e - E; }
    float alpha = ge[e] / (s[d_] + 1e-16f);
    float4 v = ((const float4*)(hf + (size_t)s_ * 32))[l8];
    red4(out + (size_t)d_ * 32 + 4 * l8, v.x * alpha, v.y * alpha, v.z * alpha, v.w * alpha);
}

// ---------------- launch ----------------
extern "C" void kernel_launch(void* const* d_in, const int* in_sizes, int n_in,
                              void* d_out, int out_size) {
    const float* x   = (const float*)d_in[0];
    const int*   ei  = (const int*)d_in[1];
    const float* W1  = (const float*)d_in[2];
    const float* aS1 = (const float*)d_in[3];
    const float* aD1 = (const float*)d_in[4];
    const float* b1  = (const float*)d_in[5];
    const float* W2  = (const float*)d_in[6];
    const float* aS2 = (const float*)d_in[7];
    const float* aD2 = (const float*)d_in[8];
    const float* b2  = (const float*)d_in[9];
    const float* Wd  = (const float*)d_in[10];
    const float* bd  = (const float*)d_in[11];
    float* out = (float*)d_out;

    int N  = in_sizes[0] / 128;
    int E  = in_sizes[1] / 2;
    int ET = E + N;
    const int* src = ei;
    const int* dst = ei + E;

    float *h1, *o1, *as1, *ad1, *s1, *h2, *z, *as2, *ad2, *s2, *e1, *e2;
    unsigned *m1, *m2;
    cudaGetSymbolAddress((void**)&h1,  g_h1);
    cudaGetSymbolAddress((void**)&o1,  g_o1);
    cudaGetSymbolAddress((void**)&as1, g_as1);
    cudaGetSymbolAddress((void**)&ad1, g_ad1);
    cudaGetSymbolAddress((void**)&m1,  g_m1);
    cudaGetSymbolAddress((void**)&s1,  g_s1);
    cudaGetSymbolAddress((void**)&e1,  g_e1);
    cudaGetSymbolAddress((void**)&h2,  g_h2);
    cudaGetSymbolAddress((void**)&z,   g_z);
    cudaGetSymbolAddress((void**)&as2, g_as2);
    cudaGetSymbolAddress((void**)&ad2, g_ad2);
    cudaGetSymbolAddress((void**)&m2,  g_m2);
    cudaGetSymbolAddress((void**)&s2,  g_s2);
    cudaGetSymbolAddress((void**)&e2,  g_e2);

    const int TB = 256;
    int mb = (N + 127) / 128;

    init_ms_k<<<(N * 8 + TB - 1) / TB, TB>>>(m1, s1, m2, s2, N);
    init_bias_k<<<(N * 256 + TB - 1) / TB, TB>>>(o1, b1, 256, N * 256);

    // ===== Layer 1 (H=8, C=32) =====
    gemm_k<<<dim3(4, mb), TB>>>(x, W1, nullptr, h1, N, 256, 128, 0);
    alpha8_k<<<(N * 32 + TB - 1) / TB, TB>>>((const float4*)h1, (const float4*)aS1,
                                             (const float4*)aD1, as1, ad1, N);
    init_bias_k<<<(N * 32 + TB - 1) / TB, TB>>>(z, b2, 32, N * 32);
    edge_logit8_k<<<(ET + TB - 1) / TB, TB>>>((const float4*)as1, (const float4*)ad1,
                                              m1, e1, src, dst, E, ET);
    edge_expsum_k<3><<<(ET * 8 + TB - 1) / TB, TB>>>(e1, m1, s1, dst, E, ET);
    edge_agg8_k<<<(unsigned)(((long long)ET * 32 + TB - 1) / TB), TB>>>(
        h1, e1, s1, o1, src, dst, E, ET);

    // ===== Layer 2 (H=1, C=32) — relu fused into GEMM A-load =====
    gemm_k<<<dim3(1, mb), TB>>>(o1, W2, nullptr, h2, N, 32, 256, 1);
    alpha1_k<<<(N * 8 + TB - 1) / TB, TB>>>((const float4*)h2, (const float4*)aS2,
                                            (const float4*)aD2, as2, ad2, N);
    edge_logit1_k<<<(ET + TB - 1) / TB, TB>>>(as2, ad2, m2, e2, src, dst, E, ET);
    edge_expsum_k<0><<<(ET + TB - 1) / TB, TB>>>(e2, m2, s2, dst, E, ET);
    edge_agg1_k<<<(unsigned)(((long long)ET * 8 + TB - 1) / TB), TB>>>(
        h2, e2, s2, z, src, dst, E, ET);

    // ===== Decoder: out = z @ Wd + bd =====
    gemm_k<<<dim3(2, mb), TB>>>(z, Wd, bd, out, N, 128, 32, 0);
}

// round 5
// speedup vs baseline: 2.7948x; 1.5260x over previous
#include <cuda_runtime.h>
#include <math.h>

static const int MAXN = 50000;
static const int MAXE = 800000 + MAXN;

// ---------------- scratch ----------------
__device__ float g_h1[MAXN * 256];
__device__ float g_o1[MAXN * 256];
__device__ float g_as1[MAXN * 8];
__device__ float g_ad1[MAXN * 8];
__device__ float g_h2[MAXN * 32];
__device__ float g_z[MAXN * 32];
__device__ float g_as2[MAXN];
__device__ float g_ad2[MAXN];
__device__ int   g_cnt[MAXN];
__device__ int   g_row[MAXN + 1];
__device__ int   g_cur[MAXN];
__device__ int   g_bsum[256];
__device__ int   g_boff[256];
__device__ int   g_esrc[MAXE];

__device__ __forceinline__ float lrelu(float v) { return v > 0.f ? v : 0.2f * v; }

// ---------------- GEMM: C[M,N] = A[M,K] @ B[K,N] (+bias), optional relu(A) ----
__global__ void gemm_k(const float* __restrict__ A, const float* __restrict__ B,
                       const float* __restrict__ bias, float* __restrict__ C,
                       int M, int N, int K, int reluA) {
    __shared__ float As[16][132];
    __shared__ float Bs[16][64];
    int tid = threadIdx.x;
    int ty = tid >> 4;
    int tx = tid & 15;
    int m0 = blockIdx.y * 128;
    int n0 = blockIdx.x * 64;
    float acc[8][4] = {};

    for (int k0 = 0; k0 < K; k0 += 16) {
        #pragma unroll
        for (int i = 0; i < 2; i++) {
            int L = tid + 256 * i;
            int row = L >> 2, q = (L & 3) << 2;
            float4 v = make_float4(0.f, 0.f, 0.f, 0.f);
            if (m0 + row < M) {
                v = *(const float4*)(A + (size_t)(m0 + row) * K + k0 + q);
                if (reluA) {
                    v.x = fmaxf(v.x, 0.f); v.y = fmaxf(v.y, 0.f);
                    v.z = fmaxf(v.z, 0.f); v.w = fmaxf(v.w, 0.f);
                }
            }
            As[q + 0][row] = v.x; As[q + 1][row] = v.y;
            As[q + 2][row] = v.z; As[q + 3][row] = v.w;
        }
        {
            int kl = tid >> 4, g = (tid & 15) << 2;
            float4 v = make_float4(0.f, 0.f, 0.f, 0.f);
            if (n0 + g < N)
                v = *(const float4*)(B + (size_t)(k0 + kl) * N + n0 + g);
            *(float4*)&Bs[kl][g] = v;
        }
        __syncthreads();
        #pragma unroll
        for (int kk = 0; kk < 16; kk++) {
            float a[8], b[4];
            *(float4*)&a[0] = *(const float4*)&As[kk][ty * 8];
            *(float4*)&a[4] = *(const float4*)&As[kk][ty * 8 + 4];
            *(float4*)&b[0] = *(const float4*)&Bs[kk][tx * 4];
            #pragma unroll
            for (int i = 0; i < 8; i++)
                #pragma unroll
                for (int j = 0; j < 4; j++)
                    acc[i][j] += a[i] * b[j];
        }
        __syncthreads();
    }
    int colb = n0 + tx * 4;
    if (colb < N) {
        float4 bv = make_float4(0.f, 0.f, 0.f, 0.f);
        if (bias) bv = *(const float4*)(bias + colb);
        #pragma unroll
        for (int i = 0; i < 8; i++) {
            int row = m0 + ty * 8 + i;
            if (row >= M) break;
            float4 v = make_float4(acc[i][0] + bv.x, acc[i][1] + bv.y,
                                   acc[i][2] + bv.z, acc[i][3] + bv.w);
            *(float4*)(C + (size_t)row * N + colb) = v;
        }
    }
}

// ---------------- attention coefficients ----------------
__global__ void alpha8_k(const float4* __restrict__ hf4,
                         const float4* __restrict__ s4, const float4* __restrict__ d4,
                         float* __restrict__ as, float* __restrict__ ad, int N) {
    int w = (blockIdx.x * blockDim.x + threadIdx.x) >> 5;
    int l = threadIdx.x & 31;
    if (w >= N) return;
    float4 cs0 = s4[l], cs1 = s4[l + 32];
    float4 cd0 = d4[l], cd1 = d4[l + 32];
    float4 h0 = hf4[(size_t)w * 64 + l];
    float4 h1 = hf4[(size_t)w * 64 + 32 + l];
    float ps0 = h0.x * cs0.x + h0.y * cs0.y + h0.z * cs0.z + h0.w * cs0.w;
    float pd0 = h0.x * cd0.x + h0.y * cd0.y + h0.z * cd0.z + h0.w * cd0.w;
    float ps1 = h1.x * cs1.x + h1.y * cs1.y + h1.z * cs1.z + h1.w * cs1.w;
    float pd1 = h1.x * cd1.x + h1.y * cd1.y + h1.z * cd1.z + h1.w * cd1.w;
    #pragma unroll
    for (int off = 4; off; off >>= 1) {
        ps0 += __shfl_xor_sync(0xffffffffu, ps0, off);
        pd0 += __shfl_xor_sync(0xffffffffu, pd0, off);
        ps1 += __shfl_xor_sync(0xffffffffu, ps1, off);
        pd1 += __shfl_xor_sync(0xffffffffu, pd1, off);
    }
    if ((l & 7) == 0) {
        int g = l >> 3;
        as[w * 8 + g] = ps0; as[w * 8 + 4 + g] = ps1;
        ad[w * 8 + g] = pd0; ad[w * 8 + 4 + g] = pd1;
    }
}

__global__ void alpha1_k(const float4* __restrict__ hf4,
                         const float4* __restrict__ s4, const float4* __restrict__ d4,
                         float* __restrict__ as, float* __restrict__ ad, int N) {
    int t = blockIdx.x * blockDim.x + threadIdx.x;
    int n = t >> 3, q = t & 7;
    if (n >= N) return;
    float4 cs = s4[q], cd = d4[q];
    float4 h = hf4[(size_t)n * 8 + q];
    float ps = h.x * cs.x + h.y * cs.y + h.z * cs.z + h.w * cs.w;
    float pd = h.x * cd.x + h.y * cd.y + h.z * cd.z + h.w * cd.w;
    #pragma unroll
    for (int off = 4; off; off >>= 1) {
        ps += __shfl_xor_sync(0xffffffffu, ps, off);
        pd += __shfl_xor_sync(0xffffffffu, pd, off);
    }
    if (q == 0) { as[n] = ps; ad[n] = pd; }
}

// ---------------- CSR build ----------------
__global__ void init_cnt_k(int* cnt, int N) {
    int i = blockIdx.x * blockDim.x + threadIdx.x;
    if (i < N) cnt[i] = 1;   // self-loop pre-counted
}
__global__ void hist_k(int* cnt, const int* __restrict__ dst, int E) {
    int e = blockIdx.x * blockDim.x + threadIdx.x;
    if (e < E) atomicAdd(&cnt[dst[e]], 1);
}
__global__ void scanA_k(const int* __restrict__ cnt, int* bsum, int N) {
    __shared__ int sm[256];
    int gi = blockIdx.x * 256 + threadIdx.x;
    int v = (gi < N) ? cnt[gi] : 0;
    sm[threadIdx.x] = v; __syncthreads();
    for (int off = 128; off; off >>= 1) {
        if (threadIdx.x < off) sm[threadIdx.x] += sm[threadIdx.x + off];
        __syncthreads();
    }
    if (threadIdx.x == 0) bsum[blockIdx.x] = sm[0];
}
__global__ void scanB_k(const int* __restrict__ bsum, int* boff, int nb) {
    __shared__ int sm[256];
    int t = threadIdx.x;
    int v = (t < nb) ? bsum[t] : 0;
    sm[t] = v; __syncthreads();
    #pragma unroll
    for (int off = 1; off < 256; off <<= 1) {
        int x = (t >= off) ? sm[t - off] : 0;
        __syncthreads();
        sm[t] += x;
        __syncthreads();
    }
    if (t < nb) boff[t] = sm[t] - v;   // exclusive
}
__global__ void scanC_k(const int* __restrict__ cnt, const int* __restrict__ boff,
                        int* row, int* cur, int N) {
    __shared__ int sm[256];
    int t = threadIdx.x;
    int gi = blockIdx.x * 256 + t;
    int v = (gi < N) ? cnt[gi] : 0;
    sm[t] = v; __syncthreads();
    #pragma unroll
    for (int off = 1; off < 256; off <<= 1) {
        int x = (t >= off) ? sm[t - off] : 0;
        __syncthreads();
        sm[t] += x;
        __syncthreads();
    }
    int excl = boff[blockIdx.x] + sm[t] - v;
    if (gi < N) { row[gi] = excl; cur[gi] = excl; }
    if (gi == N - 1) row[N] = excl + v;
}
__global__ void scatter_k(const int* __restrict__ src, const int* __restrict__ dst,
                          int* cur, int* esrc, int E, int ET) {
    int e = blockIdx.x * blockDim.x + threadIdx.x;
    if (e >= ET) return;
    int s_, d_;
    if (e < E) { s_ = src[e]; d_ = dst[e]; } else { s_ = d_ = e - E; }
    int pos = atomicAdd(&cur[d_], 1);
    esrc[pos] = s_;
}

// ---------------- fused GAT aggregate, layer 1 (H=8, C=32): warp per dst ----
__global__ void gat8_k(const float* __restrict__ h1,
                       const float* __restrict__ as, const float* __restrict__ ad,
                       const int* __restrict__ row, const int* __restrict__ esrc,
                       const float* __restrict__ bias, float* __restrict__ out, int N) {
    int w = (blockIdx.x * blockDim.x + threadIdx.x) >> 5;
    int l = threadIdx.x & 31;
    if (w >= N) return;
    int hgrp = l >> 2;
    int rs = row[w], re = row[w + 1];
    float adh = ad[w * 8 + hgrp];

    // pass 1: segment max per head (each lane walks ALL edges)
    float mx = -3.0e38f;
    int s = esrc[rs];
    for (int i = rs; i < re; i++) {
        int sn = (i + 1 < re) ? esrc[i + 1] : 0;
        float v = lrelu(__ldg(as + s * 8 + hgrp) + adh);
        mx = fmaxf(mx, v);
        s = sn;
    }
    // pass 2: exp-weighted accumulate, normalize at end
    float sum = 0.f;
    float4 acc0 = make_float4(0.f, 0.f, 0.f, 0.f);
    float4 acc1 = make_float4(0.f, 0.f, 0.f, 0.f);
    s = esrc[rs];
    for (int i = rs; i < re; i++) {
        int sn = (i + 1 < re) ? esrc[i + 1] : 0;
        float v = lrelu(__ldg(as + s * 8 + hgrp) + adh);
        float ex = expf(v - mx);
        sum += ex;
        const float4* hp = (const float4*)(h1 + (size_t)s * 256);
        float4 a = hp[2 * l], b = hp[2 * l + 1];
        acc0.x += ex * a.x; acc0.y += ex * a.y; acc0.z += ex * a.z; acc0.w += ex * a.w;
        acc1.x += ex * b.x; acc1.y += ex * b.y; acc1.z += ex * b.z; acc1.w += ex * b.w;
        s = sn;
    }
    float inv = 1.f / (sum + 1e-16f);
    float4 b0 = ((const float4*)bias)[2 * l];
    float4 b1 = ((const float4*)bias)[2 * l + 1];
    float4 o0 = make_float4(acc0.x * inv + b0.x, acc0.y * inv + b0.y,
                            acc0.z * inv + b0.z, acc0.w * inv + b0.w);
    float4 o1 = make_float4(acc1.x * inv + b1.x, acc1.y * inv + b1.y,
                            acc1.z * inv + b1.z, acc1.w * inv + b1.w);
    float4* op = (float4*)(out + (size_t)w * 256);
    op[2 * l] = o0; op[2 * l + 1] = o1;
}

// ---------------- fused GAT aggregate, layer 2 (H=1, C=32): warp per dst ----
__global__ void gat1_k(const float* __restrict__ h2,
                       const float* __restrict__ as, const float* __restrict__ ad,
                       const int* __restrict__ row, const int* __restrict__ esrc,
                       const float* __restrict__ bias, float* __restrict__ out, int N) {
    int w = (blockIdx.x * blockDim.x + threadIdx.x) >> 5;
    int l = threadIdx.x & 31;
    if (w >= N) return;
    int rs = row[w], re = row[w + 1];
    float adh = ad[w];

    float mx = -3.0e38f;
    int s = esrc[rs];
    for (int i = rs; i < re; i++) {
        int sn = (i + 1 < re) ? esrc[i + 1] : 0;
        float v = lrelu(__ldg(as + s) + adh);
        mx = fmaxf(mx, v);
        s = sn;
    }
    float sum = 0.f, acc = 0.f;
    s = esrc[rs];
    for (int i = rs; i < re; i++) {
        int sn = (i + 1 < re) ? esrc[i + 1] : 0;
        float v = lrelu(__ldg(as + s) + adh);
        float ex = expf(v - mx);
        sum += ex;
        acc += ex * __ldg(h2 + (size_t)s * 32 + l);
        s = sn;
    }
    out[(size_t)w * 32 + l] = acc / (sum + 1e-16f) + bias[l];
}

// ---------------- launch ----------------
extern "C" void kernel_launch(void* const* d_in, const int* in_sizes, int n_in,
                              void* d_out, int out_size) {
    const float* x   = (const float*)d_in[0];
    const int*   ei  = (const int*)d_in[1];
    const float* W1  = (const float*)d_in[2];
    const float* aS1 = (const float*)d_in[3];
    const float* aD1 = (const float*)d_in[4];
    const float* b1  = (const float*)d_in[5];
    const float* W2  = (const float*)d_in[6];
    const float* aS2 = (const float*)d_in[7];
    const float* aD2 = (const float*)d_in[8];
    const float* b2  = (const float*)d_in[9];
    const float* Wd  = (const float*)d_in[10];
    const float* bd  = (const float*)d_in[11];
    float* out = (float*)d_out;

    int N  = in_sizes[0] / 128;
    int E  = in_sizes[1] / 2;
    int ET = E + N;
    const int* src = ei;
    const int* dst = ei + E;

    float *h1, *o1, *as1, *ad1, *h2, *z, *as2, *ad2;
    int *cnt, *row, *cur, *bsum, *boff, *esrc;
    cudaGetSymbolAddress((void**)&h1,   g_h1);
    cudaGetSymbolAddress((void**)&o1,   g_o1);
    cudaGetSymbolAddress((void**)&as1,  g_as1);
    cudaGetSymbolAddress((void**)&ad1,  g_ad1);
    cudaGetSymbolAddress((void**)&h2,   g_h2);
    cudaGetSymbolAddress((void**)&z,    g_z);
    cudaGetSymbolAddress((void**)&as2,  g_as2);
    cudaGetSymbolAddress((void**)&ad2,  g_ad2);
    cudaGetSymbolAddress((void**)&cnt,  g_cnt);
    cudaGetSymbolAddress((void**)&row,  g_row);
    cudaGetSymbolAddress((void**)&cur,  g_cur);
    cudaGetSymbolAddress((void**)&bsum, g_bsum);
    cudaGetSymbolAddress((void**)&boff, g_boff);
    cudaGetSymbolAddress((void**)&esrc, g_esrc);

    const int TB = 256;
    int mb = (N + 127) / 128;
    int nb = (N + 255) / 256;   // <= 256

    // CSR build (+ GEMM1 interleaved; independent)
    init_cnt_k<<<nb, TB>>>(cnt, N);                                   // 1
    hist_k<<<(E + TB - 1) / TB, TB>>>(cnt, dst, E);                   // 2
    scanA_k<<<nb, TB>>>(cnt, bsum, N);                                // 3
    gemm_k<<<dim3(4, mb), TB>>>(x, W1, nullptr, h1, N, 256, 128, 0);  // 4 (profiled)
    scanB_k<<<1, TB>>>(bsum, boff, nb);                               // 5
    scanC_k<<<nb, TB>>>(cnt, boff, row, cur, N);                      // 6
    scatter_k<<<(ET + TB - 1) / TB, TB>>>(src, dst, cur, esrc, E, ET);// 7

    // ===== Layer 1 =====
    alpha8_k<<<(N * 32 + TB - 1) / TB, TB>>>((const float4*)h1, (const float4*)aS1,
                                             (const float4*)aD1, as1, ad1, N);
    gat8_k<<<(N * 32 + TB - 1) / TB, TB>>>(h1, as1, ad1, row, esrc, b1, o1, N);

    // ===== Layer 2 (relu fused into GEMM A-load) =====
    gemm_k<<<dim3(1, mb), TB>>>(o1, W2, nullptr, h2, N, 32, 256, 1);
    alpha1_k<<<(N * 8 + TB - 1) / TB, TB>>>((const float4*)h2, (const float4*)aS2,
                                            (const float4*)aD2, as2, ad2, N);
    gat1_k<<<(N * 32 + TB - 1) / TB, TB>>>(h2, as2, ad2, row, esrc, b2, z, N);

    // ===== Decoder =====
    gemm_k<<<dim3(2, mb), TB>>>(z, Wd, bd, out, N, 128, 32, 0);
}